// round 12
// baseline (speedup 1.0000x reference)
#include <cuda_runtime.h>
#include <math.h>

#define D      128
#define RREL   500
#define NNODES 200000
#define PCHAIN 8            // chain blocks (0..7), barrier scoped to these
#define PZERO  32           // zero blocks (8..39)
#define PREB   (PCHAIN + PZERO)

// ---------------- device scratch ----------------
__device__ float2 g_acc[NNODES];
__device__ float  g_w1[D];
__device__ float  g_w2[D];
__device__ float  g_p[4][D];
__device__ float  g_bdot[4];
__device__ float  g_ceff;
__device__ float  g_udot[RREL * 4];
__device__ float  g_reldot[RREL];
__device__ unsigned g_bar;          // monotonic ticket counter (graph-replay safe)

__device__ __forceinline__ float warp_sum(float v) {
#pragma unroll
    for (int o = 16; o > 0; o >>= 1) v += __shfl_down_sync(0xffffffffu, v, o);
    return v;
}

// Monotonic ticket barrier over the PCHAIN chain blocks only.
__device__ __forceinline__ void chain_barrier() {
    __syncthreads();
    if (threadIdx.x == 0) {
        __threadfence();
        unsigned old = atomicAdd(&g_bar, 1u);
        unsigned target = old - (old % PCHAIN) + PCHAIN;
        unsigned v;
        do {
            asm volatile("ld.acquire.gpu.u32 %0, [%1];" : "=r"(v) : "l"(&g_bar));
        } while (v < target);
    }
    __syncthreads();
}

// ---------------- K1: chain on 8 blocks x 1024, zeroing on 32 blocks ----------
__global__ void __launch_bounds__(1024)
k_pre(const float* __restrict__ rel_emb,
      const float* __restrict__ W_hh, const float* __restrict__ b_hh,
      const float* __restrict__ W_ht, const float* __restrict__ b_ht,
      const float* __restrict__ W_th, const float* __restrict__ b_th,
      const float* __restrict__ W_tt, const float* __restrict__ b_tt,
      const float* __restrict__ W_fin, const float* __restrict__ b_fin,
      const float* __restrict__ W_score, const float* __restrict__ b_score) {
    if (blockIdx.x >= PCHAIN) {
        // zero g_acc across PZERO blocks
        const int nt = PZERO * 1024;
        for (int i = (blockIdx.x - PCHAIN) * 1024 + threadIdx.x; i < NNODES; i += nt)
            g_acc[i] = make_float2(0.f, 0.f);
        return;
    }

    const int tid  = threadIdx.x;
    const int lane = tid & 31;
    const int gw   = blockIdx.x * 32 + (tid >> 5);   // 0..255

    // stage 0: w_eff row gw; warp 0 also does ceff
    {
        float v = 0.f;
#pragma unroll
        for (int i = 0; i < 4; i++) {
            int d = lane + 32 * i;
            v += W_fin[gw * D + d] * W_score[d];
        }
        v = warp_sum(v);
        if (lane == 0) { if (gw < D) g_w1[gw] = v; else g_w2[gw - D] = v; }
        if (gw == 0) {
            float c = 0.f;
#pragma unroll
            for (int i = 0; i < 4; i++) {
                int d = lane + 32 * i;
                c += b_fin[d] * W_score[d];
            }
            c = warp_sum(c);
            if (lane == 0) g_ceff = c + b_score[0];
        }
    }
    chain_barrier();

    // stage 1: p_x rows 2*gw, 2*gw+1; warps 0..3 also do bdot
    {
        const float* Ws[4] = {W_hh, W_ht, W_th, W_tt};
        float w1v[4];
#pragma unroll
        for (int i = 0; i < 4; i++) w1v[i] = g_w1[lane + 32 * i];
#pragma unroll
        for (int rr = 0; rr < 2; rr++) {
            int row = 2 * gw + rr;              // 0..511
            int x = row >> 7, k = row & (D - 1);
            const float* Wr = Ws[x] + k * D;
            float v = 0.f;
#pragma unroll
            for (int i = 0; i < 4; i++) v += Wr[lane + 32 * i] * w1v[i];
            v = warp_sum(v);
            if (lane == 0) g_p[x][k] = v;
        }
        if (gw < 4) {
            const float* bs[4] = {b_hh, b_ht, b_th, b_tt};
            float v = 0.f;
#pragma unroll
            for (int i = 0; i < 4; i++) v += bs[gw][lane + 32 * i] * w1v[i];
            v = warp_sum(v);
            if (lane == 0) g_bdot[gw] = v;
        }
    }
    chain_barrier();

    // stage 2: udot / reldot — relations gw and gw+256
#pragma unroll
    for (int half = 0; half < 2; half++) {
        int r = gw + half * 256;
        if (r < RREL) {
            const float* er = rel_emb + r * D;
            float e[4];
#pragma unroll
            for (int i = 0; i < 4; i++) e[i] = er[lane + 32 * i];
            float acc[5] = {0.f, 0.f, 0.f, 0.f, 0.f};
#pragma unroll
            for (int i = 0; i < 4; i++) {
                int d = lane + 32 * i;
#pragma unroll
                for (int x = 0; x < 4; x++) acc[x] += e[i] * g_p[x][d];
                acc[4] += e[i] * g_w2[d];
            }
#pragma unroll
            for (int x = 0; x < 5; x++) acc[x] = warp_sum(acc[x]);
            if (lane == 0) {
#pragma unroll
                for (int x = 0; x < 4; x++) g_udot[r * 4 + x] = acc[x];
                g_reldot[r] = acc[4];
            }
        }
    }
}

// ---------------- K2: edges, 2 per thread, front-batched ----------------
__global__ void __launch_bounds__(256)
k_edge(const int* __restrict__ ht, const int* __restrict__ r_q,
       const int* __restrict__ r_tensor, const int* __restrict__ r_relative,
       const int* __restrict__ h_or_t, const float* __restrict__ corr,
       int M, int nq) {
    const int g = blockIdx.x * 256 + threadIdx.x;
    const int ngroups = M >> 1;
    if (g < ngroups) {
        int4 ev  = ((const int4*)ht)[g];
        int2 rtv = ((const int2*)r_tensor)[g];
        int2 rqv = ((const int2*)r_q)[g];
        int2 rrv = ((const int2*)r_relative)[g];
        int2 hsv = ((const int2*)h_or_t)[g];
        int hh[2]  = {ev.x, ev.z};
        int tt[2]  = {ev.y, ev.w};
        int rta[2] = {rtv.x, rtv.y};
        int rqa[2] = {rqv.x, rqv.y};
        int rra[2] = {rrv.x, rrv.y};
        int hsa[2] = {hsv.x, hsv.y};
        float cv[2];
#pragma unroll
        for (int j = 0; j < 2; j++) cv[j] = __ldg(&corr[rta[j] * RREL + rqa[j]]);
        int mbase = g << 1;
#pragma unroll
        for (int j = 0; j < 2; j++) {
            float gate = 1.f / (1.f + __expf(-cv[j]));
            int idx = ((rra[j] == 0) ? 2 : 0) + ((hsa[j] == 0) ? 1 : 0);
            float s = gate * g_udot[rta[j] * 4 + idx] + g_bdot[idx];
            if (mbase + j < nq) s = 0.f;   // query edges: count only
            asm volatile("red.global.add.v2.f32 [%0], {%1, %2};"
                         :: "l"(&g_acc[hh[j]]), "f"(s), "f"(1.0f) : "memory");
            asm volatile("red.global.add.v2.f32 [%0], {%1, %2};"
                         :: "l"(&g_acc[tt[j]]), "f"(s), "f"(1.0f) : "memory");
        }
    }
    if ((M & 1) && blockIdx.x == 0 && threadIdx.x == 0) {
        int m = M - 1;
        int2 e = ((const int2*)ht)[m];
        int rt = r_tensor[m], rq = r_q[m];
        float c = corr[rt * RREL + rq];
        float gate = 1.f / (1.f + __expf(-c));
        int idx = ((r_relative[m] == 0) ? 2 : 0) + ((h_or_t[m] == 0) ? 1 : 0);
        float s = gate * g_udot[rt * 4 + idx] + g_bdot[idx];
        if (m < nq) s = 0.f;
        asm volatile("red.global.add.v2.f32 [%0], {%1, %2};"
                     :: "l"(&g_acc[e.x]), "f"(s), "f"(1.0f) : "memory");
        asm volatile("red.global.add.v2.f32 [%0], {%1, %2};"
                     :: "l"(&g_acc[e.y]), "f"(s), "f"(1.0f) : "memory");
    }
}

// ---------------- K3: queries, 2 per thread, front-batched gathers ----------------
__device__ __forceinline__ float2 ldcg_f2(const float2* p) {
    float2 r;
    asm volatile("ld.global.cg.v2.f32 {%0, %1}, [%2];"
                 : "=f"(r.x), "=f"(r.y) : "l"(p));
    return r;
}

__global__ void __launch_bounds__(256)
k_query(const int* __restrict__ ht, const int* __restrict__ r_tensor,
        float* __restrict__ out, int nq) {
    const int g = blockIdx.x * 256 + threadIdx.x;
    const int ngroups = nq >> 1;
    if (g < ngroups) {
        int4 ev  = ((const int4*)ht)[g];
        int2 rtv = ((const int2*)r_tensor)[g];
        int hh[2] = {ev.x, ev.z};
        int tt[2] = {ev.y, ev.w};
        float2 ah[2], at[2];
        float rd[2];
#pragma unroll
        for (int j = 0; j < 2; j++) ah[j] = ldcg_f2(&g_acc[hh[j]]);
#pragma unroll
        for (int j = 0; j < 2; j++) at[j] = ldcg_f2(&g_acc[tt[j]]);
        rd[0] = g_reldot[rtv.x];
        rd[1] = g_reldot[rtv.y];
        float2 o;
        o.x = ah[0].x / fmaxf(ah[0].y, 1.f) + at[0].x / fmaxf(at[0].y, 1.f) + rd[0] + g_ceff;
        o.y = ah[1].x / fmaxf(ah[1].y, 1.f) + at[1].x / fmaxf(at[1].y, 1.f) + rd[1] + g_ceff;
        ((float2*)out)[g] = o;
    }
    if ((nq & 1) && blockIdx.x == 0 && threadIdx.x == 0) {
        int q = nq - 1;
        int2 e = ((const int2*)ht)[q];
        float2 ah = ldcg_f2(&g_acc[e.x]);
        float2 at = ldcg_f2(&g_acc[e.y]);
        out[q] = ah.x / fmaxf(ah.y, 1.f) + at.x / fmaxf(at.y, 1.f)
               + g_reldot[r_tensor[q]] + g_ceff;
    }
}

// ---------------- launch ----------------
extern "C" void kernel_launch(void* const* d_in, const int* in_sizes, int n_in,
                              void* d_out, int out_size) {
    const int* ht         = (const int*)d_in[0];
    const int* r_q        = (const int*)d_in[1];
    const int* r_tensor   = (const int*)d_in[2];
    const int* r_relative = (const int*)d_in[3];
    const int* h_or_t     = (const int*)d_in[4];
    int base = n_in - 14;
    const float* rel_emb = (const float*)d_in[base + 0];
    const float* corr    = (const float*)d_in[base + 1];
    const float* W_hh    = (const float*)d_in[base + 2];
    const float* b_hh    = (const float*)d_in[base + 3];
    const float* W_ht    = (const float*)d_in[base + 4];
    const float* b_ht    = (const float*)d_in[base + 5];
    const float* W_th    = (const float*)d_in[base + 6];
    const float* b_th    = (const float*)d_in[base + 7];
    const float* W_tt    = (const float*)d_in[base + 8];
    const float* b_tt    = (const float*)d_in[base + 9];
    const float* W_fin   = (const float*)d_in[base + 10];
    const float* b_fin   = (const float*)d_in[base + 11];
    const float* W_score = (const float*)d_in[base + 12];
    const float* b_score = (const float*)d_in[base + 13];

    int M  = in_sizes[0] / 2;
    int nq = out_size;

    k_pre<<<PREB, 1024>>>(rel_emb, W_hh, b_hh, W_ht, b_ht, W_th, b_th,
                          W_tt, b_tt, W_fin, b_fin, W_score, b_score);
    int eg = M >> 1;
    k_edge<<<(eg + 255) / 256, 256>>>(ht, r_q, r_tensor, r_relative, h_or_t,
                                      corr, M, nq);
    int qg = nq >> 1;
    k_query<<<(qg + 255) / 256 + (qg == 0), 256>>>(ht, r_tensor, (float*)d_out, nq);
}